// round 1
// baseline (speedup 1.0000x reference)
#include <cuda_runtime.h>
#include <cuda_bf16.h>

// VanillaRNN: diagonal recurrence h <- tanh(x_t * w_in + h * w_diag + b_h),
// then out = h_final @ W_hp^T + b_o.
// Shapes: x (1024,1024), W_hx (256,1), W_hh (256,256), b_h (256),
//         W_hp (10,256), b_o (10). out (1024,10) float32.

#define RB 1024   // batch
#define RT 1024   // time steps
#define RH 256    // hidden
#define RC 10     // classes

__device__ __forceinline__ float ex2_approx(float x) {
    float r;
    asm("ex2.approx.f32 %0, %1;" : "=f"(r) : "f"(x));
    return r;
}
__device__ __forceinline__ float rcp_approx(float x) {
    float r;
    asm("rcp.approx.f32 %0, %1;" : "=f"(r) : "f"(x));
    return r;
}

// Accurate-enough tanh: tanh(z) = sign(z) * (1 - e) / (1 + e), e = 2^(-2|z|/ln2)
// ex2.approx + rcp.approx -> ~1e-6 abs error. 2 MUFU + ~7 FMA/ALU per call.
__device__ __forceinline__ float tanh_fast(float z) {
    float za = fabsf(z);
    float e  = ex2_approx(za * -2.8853900817779268f);  // e^{-2|z|}
    float num = 1.0f - e;
    float den = 1.0f + e;
    float r = num * rcp_approx(den);
    return copysignf(r, z);
}

__global__ __launch_bounds__(RH, 8)
void vanilla_rnn_kernel(const float* __restrict__ x,
                        const float* __restrict__ W_hx,
                        const float* __restrict__ W_hh,
                        const float* __restrict__ b_h,
                        const float* __restrict__ W_hp,
                        const float* __restrict__ b_o,
                        float* __restrict__ out)
{
    __shared__ float xs[RT];     // this block's x row (4 KB)
    __shared__ float hs[RH];     // final hidden state for epilogue

    const int b = blockIdx.x;
    const int h = threadIdx.x;

    // Stage x[b, :] into shared memory: 256 threads x 1 float4 each = 1024 floats.
    {
        const float4* xrow = reinterpret_cast<const float4*>(x + (size_t)b * RT);
        reinterpret_cast<float4*>(xs)[h] = xrow[h];
    }

    // Per-thread constants
    const float wi = W_hx[h];           // W_hx[h, 0]
    const float wd = W_hh[h * RH + h];  // diag(W_hh)[h]
    const float bh = b_h[h];

    __syncthreads();

    float hv = 0.0f;
    #pragma unroll 8
    for (int t = 0; t < RT; t++) {
        float z = fmaf(xs[t], wi, fmaf(hv, wd, bh));
        hv = tanh_fast(z);
    }

    hs[h] = hv;
    __syncthreads();

    // Epilogue: out[b, c] = sum_h hs[h] * W_hp[c, h] + b_o[c]
    if (h < RC) {
        const float* wrow = W_hp + h * RH;
        float acc = b_o[h];
        #pragma unroll 8
        for (int j = 0; j < RH; j++)
            acc = fmaf(hs[j], wrow[j], acc);
        out[b * RC + h] = acc;
    }
}

extern "C" void kernel_launch(void* const* d_in, const int* in_sizes, int n_in,
                              void* d_out, int out_size)
{
    const float* x    = (const float*)d_in[0];
    const float* W_hx = (const float*)d_in[1];
    const float* W_hh = (const float*)d_in[2];
    const float* b_h  = (const float*)d_in[3];
    const float* W_hp = (const float*)d_in[4];
    const float* b_o  = (const float*)d_in[5];
    float* out = (float*)d_out;

    vanilla_rnn_kernel<<<RB, RH>>>(x, W_hx, W_hh, b_h, W_hp, b_o, out);
}

// round 2
// speedup vs baseline: 2.2118x; 2.2118x over previous
#include <cuda_runtime.h>
#include <cuda_bf16.h>

// VanillaRNN: diagonal recurrence h <- tanh(x_t * w_in + h * w_diag + b_h),
// then out = h_final @ W_hp^T + b_o.
// Shapes: x (1024,1024), W_hx (256,1), W_hh (256,256), b_h (256),
//         W_hp (10,256), b_o (10). out (1024,10) float32.

#define RB 1024   // batch
#define RT 1024   // time steps
#define RH 256    // hidden
#define RC 10     // classes

// HW tanh: single MUFU.TANH on sm_75+ (abs err ~2^-11).
__device__ __forceinline__ float tanh_hw(float x) {
    float r;
    asm("tanh.approx.f32 %0, %1;" : "=f"(r) : "f"(x));
    return r;
}

__global__ __launch_bounds__(RH, 8)
void vanilla_rnn_kernel(const float* __restrict__ x,
                        const float* __restrict__ W_hx,
                        const float* __restrict__ W_hh,
                        const float* __restrict__ b_h,
                        const float* __restrict__ W_hp,
                        const float* __restrict__ b_o,
                        float* __restrict__ out)
{
    __shared__ float xs[RT];     // this block's x row (4 KB)
    __shared__ float hs[RH];     // final hidden state for epilogue

    const int b = blockIdx.x;
    const int h = threadIdx.x;

    // Stage x[b, :]: 256 threads x 1 float4 = 1024 floats.
    {
        const float4* xrow = reinterpret_cast<const float4*>(x + (size_t)b * RT);
        reinterpret_cast<float4*>(xs)[h] = xrow[h];
    }

    const float wi = W_hx[h];           // W_hx[h, 0]
    const float wd = W_hh[h * RH + h];  // diag(W_hh)[h]
    const float bh = b_h[h];

    __syncthreads();

    float hv = 0.0f;
    #pragma unroll 16
    for (int t = 0; t < RT; t++) {
        float z = fmaf(xs[t], wi, fmaf(hv, wd, bh));
        hv = tanh_hw(z);
    }

    hs[h] = hv;
    __syncthreads();

    // Epilogue: out[b, c] = sum_h hs[h] * W_hp[c, h] + b_o[c]
    if (h < RC) {
        const float* wrow = W_hp + h * RH;
        float acc = b_o[h];
        #pragma unroll 8
        for (int j = 0; j < RH; j++)
            acc = fmaf(hs[j], wrow[j], acc);
        out[b * RC + h] = acc;
    }
}

extern "C" void kernel_launch(void* const* d_in, const int* in_sizes, int n_in,
                              void* d_out, int out_size)
{
    const float* x    = (const float*)d_in[0];
    const float* W_hx = (const float*)d_in[1];
    const float* W_hh = (const float*)d_in[2];
    const float* b_h  = (const float*)d_in[3];
    const float* W_hp = (const float*)d_in[4];
    const float* b_o  = (const float*)d_in[5];
    float* out = (float*)d_out;

    vanilla_rnn_kernel<<<RB, RH>>>(x, W_hx, W_hh, b_h, W_hp, b_o, out);
}